// round 9
// baseline (speedup 1.0000x reference)
#include <cuda_runtime.h>
#include <cuda_bf16.h>
#include <cstdint>

// ============================================================================
// LocalBranch round 9: bf16x3 mma.sync, M-split 2 CTAs/SM.
//  Kernel A (mlp): 2048 CTAs x 256 thr; each CTA runs 64 nodes through
//    stem + 3 residual blocks + head; z -> __device__ scratch.
//    Weights: k16 chunks, LDG->reg->STS single-slot prefetch (94KB smem).
//  Kernel B (pool): 1024 CTAs x 256 thr; Gram = Z@Z^T via bf16x3 mma from
//    smem planes; distances, softmax, weighted pool.
// ============================================================================

namespace lb {

using u32 = uint32_t;

constexpr int NODES = 128, IND = 64, HID = 256, OUTD = 128, NBLK = 3, NG = 1024;

// ---- kernel A smem ----
constexpr int TPA   = 256;
constexpr int XA_RS = 528;              // x-plane row stride (bytes)
constexpr int XA_PL = 64 * XA_RS;       // 33792 per plane (64 rows)
constexpr int A_SLOT = 2 * XA_PL;       // weight slot @67584 (24576 B max)
constexpr int A_PART = A_SLOT + 24576;  // float2[256] @92160
constexpr int SMEM_A = A_PART + 2048;   // 94208

// ---- kernel B smem ----
constexpr int TPBB  = 256;
constexpr int ZB_RS = 272;              // z-plane row stride (bytes)
constexpr int ZB_PL = 128 * ZB_RS;      // 34816 per plane
constexpr int B_SQ   = 2 * ZB_PL;       // float[128] @69632
constexpr int B_PART = B_SQ + 512;      // float[256]
constexpr int B_SSM  = B_PART + 1024;   // float[128]
constexpr int B_WSM  = B_SSM + 512;     // float[128]
constexpr int B_VP   = B_WSM + 512;     // float[256]
constexpr int SMEM_B = B_VP + 1024;     // 73216

// ---- weight image: k16 chunks, rows 48 B (32 data + 16 pad), n-major;
//      chunk = [hi plane N*48][lo plane N*48] ----
constexpr long IMG_STEM   = 0;                       // 4 chunks x 24576
constexpr long IMG_BLK    = 98304;                   // 3 x 16 x 24576
constexpr long IMG_BLKSTR = 393216;
constexpr long IMG_HEAD   = 1277952;                 // 16 x 12288
__device__ __align__(16) unsigned char g_wimg[1474560];
__device__ float g_z[(size_t)NG * NODES * OUTD];     // 64 MB scratch

// ---------------- PTX helpers ----------------
__device__ __forceinline__ u32 s2u(const void* p) {
    u32 a;
    asm("{ .reg .u64 t; cvta.to.shared.u64 t, %1; cvt.u32.u64 %0, t; }"
        : "=r"(a) : "l"(p));
    return a;
}
__device__ __forceinline__ void ldsm4(u32* r, u32 addr) {
    asm volatile("ldmatrix.sync.aligned.m8n8.x4.shared.b16 {%0,%1,%2,%3}, [%4];"
                 : "=r"(r[0]), "=r"(r[1]), "=r"(r[2]), "=r"(r[3]) : "r"(addr));
}
__device__ __forceinline__ void mma16816(float* c, const u32* a, u32 b0, u32 b1) {
    asm volatile(
        "mma.sync.aligned.m16n8k16.row.col.f32.bf16.bf16.f32 "
        "{%0,%1,%2,%3}, {%4,%5,%6,%7}, {%8,%9}, {%0,%1,%2,%3};"
        : "+f"(c[0]), "+f"(c[1]), "+f"(c[2]), "+f"(c[3])
        : "r"(a[0]), "r"(a[1]), "r"(a[2]), "r"(a[3]), "r"(b0), "r"(b1));
}

// ---------------- bf16 pack helpers ----------------
__device__ __forceinline__ u32 packbf(float x0, float x1) {
    unsigned short a = __bfloat16_as_ushort(__float2bfloat16(x0));
    unsigned short b = __bfloat16_as_ushort(__float2bfloat16(x1));
    return (u32)a | ((u32)b << 16);
}
__device__ __forceinline__ float bflo(u32 p) {
    return __bfloat162float(__ushort_as_bfloat16((unsigned short)(p & 0xffff)));
}
__device__ __forceinline__ float bfhi(u32 p) {
    return __bfloat162float(__ushort_as_bfloat16((unsigned short)(p >> 16)));
}
__device__ __forceinline__ float bf2f(unsigned short v) {
    return __bfloat162float(__ushort_as_bfloat16(v));
}
__device__ __forceinline__ float warpsum(float v) {
#pragma unroll
    for (int o = 16; o; o >>= 1) v += __shfl_xor_sync(0xffffffffu, v, o);
    return v;
}

// ---------------- prep: weights -> split/transposed k16-chunk image --------
__global__ void prep(const float* __restrict__ Wi, const float* __restrict__ Wb,
                     const float* __restrict__ Wo) {
    int idx = blockIdx.x * 256 + threadIdx.x;        // 245760 total
    const float* W; int k, n, N; long base;
    if (idx < 16384) {
        W = Wi; N = 256; k = idx >> 8; n = idx & 255; base = IMG_STEM;
    } else if (idx < 212992) {
        int e = idx - 16384; int b = e >> 16; e &= 65535;
        W = Wb + (size_t)b * 65536; N = 256; k = e >> 8; n = e & 255;
        base = IMG_BLK + (long)b * IMG_BLKSTR;
    } else {
        int e = idx - 212992;
        W = Wo; N = 128; k = e >> 7; n = e & 127; base = IMG_HEAD;
    }
    float w = W[(size_t)k * N + n];
    __nv_bfloat16 h = __float2bfloat16(w);
    __nv_bfloat16 l = __float2bfloat16(w - __bfloat162float(h));
    long chunkB = (long)N * 96;
    long off = base + (long)(k >> 4) * chunkB + (long)n * 48 + (k & 15) * 2;
    *(__nv_bfloat16*)(g_wimg + off) = h;
    *(__nv_bfloat16*)(g_wimg + off + (long)N * 48) = l;
}

// ---------------- kernel A staged GEMM (k16 chunks, reg prefetch) ----------
template<int N>   // 256 or 128
__device__ __forceinline__ void gemmA(
    u32 smb, unsigned char* smc, const unsigned char* img, int nchunk,
    float (&acc)[2][8][4], int tid, int m0, int nq,
    int a_row, int a_kh, int b_n, int b_kh)
{
    constexpr int CB = N * 96;             // chunk bytes
    constexpr int PF = CB / (TPA * 16);    // float4 per thread (6 or 3)
    constexpr int NH = N / 128;            // n16-pair groups per warp (2 or 1)
    const int n0 = nq * (N / 4);

    const u32 axh = smb + (u32)(m0 + a_row) * XA_RS + a_kh * 16;
    const u32 axl = axh + XA_PL;
    const u32 slotb = smb + A_SLOT;
    const u32 wtb = (u32)(n0 + b_n) * 48 + b_kh * 16;

#pragma unroll
    for (int mt = 0; mt < 2; ++mt)
#pragma unroll
        for (int nt = 0; nt < 8; ++nt)
#pragma unroll
            for (int e = 0; e < 4; ++e) acc[mt][nt][e] = 0.f;

    float4 pre[PF];
    {
        const float4* s4 = (const float4*)img;
#pragma unroll
        for (int q = 0; q < PF; ++q) pre[q] = s4[tid + q * TPA];
    }

    for (int ch = 0; ch < nchunk; ++ch) {
        __syncthreads();                   // slot free (prev consumers done)
        {
            float4* d4 = (float4*)(smc + A_SLOT);
#pragma unroll
            for (int q = 0; q < PF; ++q) d4[tid + q * TPA] = pre[q];
        }
        __syncthreads();
        if (ch + 1 < nchunk) {
            const float4* s4 = (const float4*)(img + (size_t)(ch + 1) * CB);
#pragma unroll
            for (int q = 0; q < PF; ++q) pre[q] = s4[tid + q * TPA];
        }
        const u32 kb = (u32)ch * 32;       // 16 k-values = 32 B in x planes
        u32 ah0[4], ah1[4], al0[4], al1[4];
        ldsm4(ah0, axh + kb);
        ldsm4(ah1, axh + 16 * XA_RS + kb);
        ldsm4(al0, axl + kb);
        ldsm4(al1, axl + 16 * XA_RS + kb);
#pragma unroll
        for (int hf = 0; hf < NH; ++hf) {
            u32 bh[2][4], bl[2][4];
#pragma unroll
            for (int p = 0; p < 2; ++p) {
                const u32 wa = slotb + wtb + (u32)(hf * 2 + p) * 16 * 48;
                ldsm4(bh[p], wa);
                ldsm4(bl[p], wa + N * 48);
            }
#pragma unroll
            for (int p = 0; p < 2; ++p)
#pragma unroll
                for (int h = 0; h < 2; ++h) {
                    int nt = (hf * 2 + p) * 2 + h;
                    mma16816(acc[0][nt], ah0, bh[p][2*h], bh[p][2*h+1]);
                    mma16816(acc[1][nt], ah1, bh[p][2*h], bh[p][2*h+1]);
                }
#pragma unroll
            for (int p = 0; p < 2; ++p)
#pragma unroll
                for (int h = 0; h < 2; ++h) {
                    int nt = (hf * 2 + p) * 2 + h;
                    mma16816(acc[0][nt], al0, bh[p][2*h], bh[p][2*h+1]);
                    mma16816(acc[1][nt], al1, bh[p][2*h], bh[p][2*h+1]);
                }
#pragma unroll
            for (int p = 0; p < 2; ++p)
#pragma unroll
                for (int h = 0; h < 2; ++h) {
                    int nt = (hf * 2 + p) * 2 + h;
                    mma16816(acc[0][nt], ah0, bl[p][2*h], bl[p][2*h+1]);
                    mma16816(acc[1][nt], ah1, bl[p][2*h], bl[p][2*h+1]);
                }
        }
    }
}

// ---------------- kernel A: MLP over 64 nodes ----------------
__global__ void __launch_bounds__(TPA, 2)
mlp(const float* __restrict__ H,
    const float* __restrict__ b_in, const float* __restrict__ g_in,
    const float* __restrict__ be_in,
    const float* __restrict__ bb, const float* __restrict__ gb,
    const float* __restrict__ betab,
    const float* __restrict__ b_out, const float* __restrict__ g_out,
    const float* __restrict__ be_out)
{
    extern __shared__ __align__(16) unsigned char smc[];
    const u32 smb = s2u(smc);
    const int tid = threadIdx.x, lane = tid & 31, w = tid >> 5;
    const int qr = lane >> 2, qc = lane & 3;
    const int m0 = (w & 1) * 32, nq = w >> 1;
    const int grp = lane >> 3, ri = lane & 7;
    const int a_row = (grp & 1) * 8 + ri, a_kh = grp >> 1;
    const int b_n = (grp >> 1) * 8 + ri,  b_kh = grp & 1;
    const int g = blockIdx.x >> 1, mh = blockIdx.x & 1;

    float2* part = (float2*)(smc + A_PART);

    // ---- load H (64 rows, node base mh*64) -> hi/lo planes ----
    {
        const int row = tid >> 2, c4 = tid & 3;
        const float4* hs = (const float4*)(H + (size_t)g * NODES * IND
                                           + (size_t)(mh * 64 + row) * IND
                                           + c4 * 16);
        const u32 off = (u32)row * XA_RS + (u32)c4 * 32;
#pragma unroll
        for (int q = 0; q < 4; ++q) {
            float4 v = hs[q];
            u32 h0 = packbf(v.x, v.y), h1 = packbf(v.z, v.w);
            u32 l0 = packbf(v.x - bflo(h0), v.y - bfhi(h0));
            u32 l1 = packbf(v.z - bflo(h1), v.w - bfhi(h1));
            *(u32*)(smc + off + q * 8)             = h0;
            *(u32*)(smc + off + q * 8 + 4)         = h1;
            *(u32*)(smc + XA_PL + off + q * 8)     = l0;
            *(u32*)(smc + XA_PL + off + q * 8 + 4) = l1;
        }
    }
    // (gemmA's loop-top __syncthreads orders these STS before ldmatrix)

    float acc[2][8][4];

    // ---- LN(+relu,+residual) epilogue N=256, rewrites x planes ----
    auto ep256 = [&](const float* bias, const float* gam, const float* bet,
                     bool res) {
        const int n0 = nq * 64;
        float s1[4] = {0.f, 0.f, 0.f, 0.f}, s2[4] = {0.f, 0.f, 0.f, 0.f};
#pragma unroll
        for (int nt = 0; nt < 8; ++nt) {
            float2 bp = *(const float2*)&bias[n0 + nt * 8 + qc * 2];
#pragma unroll
            for (int mt = 0; mt < 2; ++mt) {
                float* c = acc[mt][nt];
                c[0] += bp.x; c[1] += bp.y; c[2] += bp.x; c[3] += bp.y;
                s1[mt*2]   += c[0] + c[1];
                s2[mt*2]    = fmaf(c[0], c[0], fmaf(c[1], c[1], s2[mt*2]));
                s1[mt*2+1] += c[2] + c[3];
                s2[mt*2+1]  = fmaf(c[2], c[2], fmaf(c[3], c[3], s2[mt*2+1]));
            }
        }
#pragma unroll
        for (int r = 0; r < 4; ++r) {
            s1[r] += __shfl_xor_sync(0xffffffffu, s1[r], 1);
            s1[r] += __shfl_xor_sync(0xffffffffu, s1[r], 2);
            s2[r] += __shfl_xor_sync(0xffffffffu, s2[r], 1);
            s2[r] += __shfl_xor_sync(0xffffffffu, s2[r], 2);
        }
        __syncthreads();   // prev gemm slot consumers done; safe to reuse part
        if (qc == 0) {
#pragma unroll
            for (int r = 0; r < 4; ++r) {
                int row = m0 + (r >> 1) * 16 + (r & 1) * 8 + qr;
                part[row * 4 + nq] = make_float2(s1[r], s2[r]);
            }
        }
        __syncthreads();
        float mu[4], rs[4];
#pragma unroll
        for (int r = 0; r < 4; ++r) {
            int row = m0 + (r >> 1) * 16 + (r & 1) * 8 + qr;
            float4 p0 = *(float4*)&part[row * 4];
            float4 p1 = *(float4*)&part[row * 4 + 2];
            float S1 = p0.x + p0.z + p1.x + p1.z;
            float S2 = p0.y + p0.w + p1.y + p1.w;
            float m_ = S1 * (1.f / 256.f);
            mu[r] = m_;
            rs[r] = rsqrtf(fmaf(-m_, m_, S2 * (1.f / 256.f)) + 1e-5f);
        }
        __syncthreads();
#pragma unroll
        for (int nt = 0; nt < 8; ++nt) {
            int col = n0 + nt * 8 + qc * 2;
            float2 gg = *(const float2*)&gam[col];
            float2 ee = *(const float2*)&bet[col];
#pragma unroll
            for (int mt = 0; mt < 2; ++mt)
#pragma unroll
                for (int h = 0; h < 2; ++h) {
                    int r4 = mt * 2 + h;
                    int row = m0 + mt * 16 + h * 8 + qr;
                    float v0 = acc[mt][nt][2 * h], v1 = acc[mt][nt][2 * h + 1];
                    float y0 = fmaxf(fmaf((v0 - mu[r4]) * rs[r4], gg.x, ee.x), 0.f);
                    float y1 = fmaxf(fmaf((v1 - mu[r4]) * rs[r4], gg.y, ee.y), 0.f);
                    u32 off = (u32)row * XA_RS + (u32)col * 2;
                    if (res) {
                        u32 oh = *(u32*)(smc + off);
                        u32 ol = *(u32*)(smc + XA_PL + off);
                        y0 += bflo(oh) + bflo(ol);
                        y1 += bfhi(oh) + bfhi(ol);
                    }
                    u32 hh = packbf(y0, y1);
                    u32 ll = packbf(y0 - bflo(hh), y1 - bfhi(hh));
                    *(u32*)(smc + off)         = hh;
                    *(u32*)(smc + XA_PL + off) = ll;
                }
        }
        __syncthreads();
    };

    // ---- pipeline ----
    gemmA<256>(smb, smc, g_wimg + IMG_STEM, 4, acc, tid, m0, nq,
               a_row, a_kh, b_n, b_kh);
    ep256(b_in, g_in, be_in, false);
    for (int b = 0; b < NBLK; ++b) {
        gemmA<256>(smb, smc, g_wimg + IMG_BLK + (size_t)b * IMG_BLKSTR, 16,
                   acc, tid, m0, nq, a_row, a_kh, b_n, b_kh);
        ep256(bb + b * HID, gb + b * HID, betab + b * HID, true);
    }
    gemmA<128>(smb, smc, g_wimg + IMG_HEAD, 16, acc, tid, m0, nq,
               a_row, a_kh, b_n, b_kh);

    // ---- head epilogue: z = LN(.), write to g_z ----
    {
        const int n0 = nq * 32;
        float s1[4] = {0.f, 0.f, 0.f, 0.f}, s2[4] = {0.f, 0.f, 0.f, 0.f};
#pragma unroll
        for (int nt = 0; nt < 4; ++nt) {
            float2 bp = *(const float2*)&b_out[n0 + nt * 8 + qc * 2];
#pragma unroll
            for (int mt = 0; mt < 2; ++mt) {
                float* c = acc[mt][nt];
                c[0] += bp.x; c[1] += bp.y; c[2] += bp.x; c[3] += bp.y;
                s1[mt*2]   += c[0] + c[1];
                s2[mt*2]    = fmaf(c[0], c[0], fmaf(c[1], c[1], s2[mt*2]));
                s1[mt*2+1] += c[2] + c[3];
                s2[mt*2+1]  = fmaf(c[2], c[2], fmaf(c[3], c[3], s2[mt*2+1]));
            }
        }
#pragma unroll
        for (int r = 0; r < 4; ++r) {
            s1[r] += __shfl_xor_sync(0xffffffffu, s1[r], 1);
            s1[r] += __shfl_xor_sync(0xffffffffu, s1[r], 2);
            s2[r] += __shfl_xor_sync(0xffffffffu, s2[r], 1);
            s2[r] += __shfl_xor_sync(0xffffffffu, s2[r], 2);
        }
        __syncthreads();
        if (qc == 0) {
#pragma unroll
            for (int r = 0; r < 4; ++r) {
                int row = m0 + (r >> 1) * 16 + (r & 1) * 8 + qr;
                part[row * 4 + nq] = make_float2(s1[r], s2[r]);
            }
        }
        __syncthreads();
        float mu[4], rs[4];
#pragma unroll
        for (int r = 0; r < 4; ++r) {
            int row = m0 + (r >> 1) * 16 + (r & 1) * 8 + qr;
            float4 p0 = *(float4*)&part[row * 4];
            float4 p1 = *(float4*)&part[row * 4 + 2];
            float S1 = p0.x + p0.z + p1.x + p1.z;
            float S2 = p0.y + p0.w + p1.y + p1.w;
            float m_ = S1 * (1.f / 128.f);
            mu[r] = m_;
            rs[r] = rsqrtf(fmaf(-m_, m_, S2 * (1.f / 128.f)) + 1e-5f);
        }
        float* zbase = g_z + (size_t)g * (NODES * OUTD);
#pragma unroll
        for (int nt = 0; nt < 4; ++nt) {
            int col = n0 + nt * 8 + qc * 2;
            float2 gg = *(const float2*)&g_out[col];
            float2 ee = *(const float2*)&be_out[col];
#pragma unroll
            for (int mt = 0; mt < 2; ++mt)
#pragma unroll
                for (int h = 0; h < 2; ++h) {
                    int r4 = mt * 2 + h;
                    int row = m0 + mt * 16 + h * 8 + qr;
                    float z0 = fmaf((acc[mt][nt][2*h]   - mu[r4]) * rs[r4], gg.x, ee.x);
                    float z1 = fmaf((acc[mt][nt][2*h+1] - mu[r4]) * rs[r4], gg.y, ee.y);
                    *(float2*)(zbase + (size_t)(mh * 64 + row) * OUTD + col) =
                        make_float2(z0, z1);
                }
        }
    }
}

// ---------------- kernel B: Gram + distances + softmax + pool ----------------
__global__ void __launch_bounds__(TPBB, 3)
pool(float* __restrict__ out)
{
    extern __shared__ __align__(16) unsigned char smc[];
    const u32 smb = s2u(smc);
    const int tid = threadIdx.x, lane = tid & 31, w = tid >> 5;
    const int qr = lane >> 2, qc = lane & 3;
    const int m0 = (w & 3) * 32, nh = w >> 2;
    const int n0 = nh * 64;
    const int grp = lane >> 3, ri = lane & 7;
    const int a_row = (grp & 1) * 8 + ri, a_kh = grp >> 1;
    const int b_n = (grp >> 1) * 8 + ri,  b_kh = grp & 1;
    const int g = blockIdx.x;

    float* sqf  = (float*)(smc + B_SQ);
    float* partf = (float*)(smc + B_PART);
    float* ssm  = (float*)(smc + B_SSM);
    float* wsm  = (float*)(smc + B_WSM);
    float* vpart = (float*)(smc + B_VP);

    // ---- load z, convert to hi/lo planes, row norms ----
    const float* zbase = g_z + (size_t)g * (NODES * OUTD);
#pragma unroll 1
    for (int j = 0; j < 16; ++j) {
        int r = w * 16 + j;
        float4 v = ((const float4*)(zbase + (size_t)r * OUTD))[lane];
        u32 h0 = packbf(v.x, v.y), h1 = packbf(v.z, v.w);
        u32 l0 = packbf(v.x - bflo(h0), v.y - bfhi(h0));
        u32 l1 = packbf(v.z - bflo(h1), v.w - bfhi(h1));
        u32 off = (u32)r * ZB_RS + (u32)lane * 8;
        *(u32*)(smc + off)             = h0;
        *(u32*)(smc + off + 4)         = h1;
        *(u32*)(smc + ZB_PL + off)     = l0;
        *(u32*)(smc + ZB_PL + off + 4) = l1;
        float sq = fmaf(v.x, v.x, fmaf(v.y, v.y, fmaf(v.z, v.z, v.w * v.w)));
        sq = warpsum(sq);
        if (lane == 0) sqf[r] = sq;
    }
    __syncthreads();

    // ---- Gram via bf16x3 mma (warp tile 32x64) ----
    float acc[2][8][4];
#pragma unroll
    for (int mt = 0; mt < 2; ++mt)
#pragma unroll
        for (int nt = 0; nt < 8; ++nt)
#pragma unroll
            for (int e = 0; e < 4; ++e) acc[mt][nt][e] = 0.f;

    const u32 azh = smb + (u32)(m0 + a_row) * ZB_RS + a_kh * 16;
    const u32 azl = azh + ZB_PL;
    const u32 bzh = smb + (u32)(n0 + b_n) * ZB_RS + b_kh * 16;
    const u32 bzl = bzh + ZB_PL;
#pragma unroll
    for (int ks = 0; ks < 8; ++ks) {
        const u32 kb = (u32)ks * 32;
        u32 ah0[4], ah1[4], al0[4], al1[4];
        ldsm4(ah0, azh + kb);
        ldsm4(ah1, azh + 16 * ZB_RS + kb);
        ldsm4(al0, azl + kb);
        ldsm4(al1, azl + 16 * ZB_RS + kb);
#pragma unroll
        for (int hf = 0; hf < 2; ++hf) {
            u32 bh[2][4], bl[2][4];
#pragma unroll
            for (int p = 0; p < 2; ++p) {
                const u32 wa = (u32)(hf * 2 + p) * 16 * ZB_RS + kb;
                ldsm4(bh[p], bzh + wa);
                ldsm4(bl[p], bzl + wa);
            }
#pragma unroll
            for (int p = 0; p < 2; ++p)
#pragma unroll
                for (int h = 0; h < 2; ++h) {
                    int nt = (hf * 2 + p) * 2 + h;
                    mma16816(acc[0][nt], ah0, bh[p][2*h], bh[p][2*h+1]);
                    mma16816(acc[1][nt], ah1, bh[p][2*h], bh[p][2*h+1]);
                }
#pragma unroll
            for (int p = 0; p < 2; ++p)
#pragma unroll
                for (int h = 0; h < 2; ++h) {
                    int nt = (hf * 2 + p) * 2 + h;
                    mma16816(acc[0][nt], al0, bh[p][2*h], bh[p][2*h+1]);
                    mma16816(acc[1][nt], al1, bh[p][2*h], bh[p][2*h+1]);
                }
#pragma unroll
            for (int p = 0; p < 2; ++p)
#pragma unroll
                for (int h = 0; h < 2; ++h) {
                    int nt = (hf * 2 + p) * 2 + h;
                    mma16816(acc[0][nt], ah0, bl[p][2*h], bl[p][2*h+1]);
                    mma16816(acc[1][nt], ah1, bl[p][2*h], bl[p][2*h+1]);
                }
        }
    }

    // ---- distances -> per-row sums ----
    float sa[4] = {0.f, 0.f, 0.f, 0.f};
#pragma unroll
    for (int nt = 0; nt < 8; ++nt) {
        int col = n0 + nt * 8 + qc * 2;
        float sc0 = sqf[col], sc1 = sqf[col + 1];
#pragma unroll
        for (int mt = 0; mt < 2; ++mt)
#pragma unroll
            for (int h = 0; h < 2; ++h) {
                int r4 = mt * 2 + h;
                int row = m0 + mt * 16 + h * 8 + qr;
                float sr = sqf[row];
                float d0 = sr + sc0 - 2.f * acc[mt][nt][2 * h];
                float d1 = sr + sc1 - 2.f * acc[mt][nt][2 * h + 1];
                float t0 = (col == row) ? 1e-6f : sqrtf(fmaxf(d0, 0.f) + 1e-12f);
                float t1 = (col + 1 == row) ? 1e-6f : sqrtf(fmaxf(d1, 0.f) + 1e-12f);
                sa[r4] += t0 + t1;
            }
    }
#pragma unroll
    for (int r = 0; r < 4; ++r) {
        sa[r] += __shfl_xor_sync(0xffffffffu, sa[r], 1);
        sa[r] += __shfl_xor_sync(0xffffffffu, sa[r], 2);
    }
    if (qc == 0) {
#pragma unroll
        for (int r = 0; r < 4; ++r) {
            int row = m0 + (r >> 1) * 16 + (r & 1) * 8 + qr;
            partf[row * 2 + nh] = sa[r];
        }
    }
    __syncthreads();
    if (tid < NODES)
        ssm[tid] = (partf[tid * 2] + partf[tid * 2 + 1]) * (1.f / 128.f);
    __syncthreads();

    // ---- softmax (warp 0) ----
    if (w == 0) {
        const float sc = 1.f / 0.25f;
        float sv[4], mx = -1e30f;
#pragma unroll
        for (int q = 0; q < 4; ++q) {
            sv[q] = ssm[lane + 32 * q] * sc;
            mx = fmaxf(mx, sv[q]);
        }
#pragma unroll
        for (int o = 16; o; o >>= 1)
            mx = fmaxf(mx, __shfl_xor_sync(0xffffffffu, mx, o));
        float e[4], se = 0.f;
#pragma unroll
        for (int q = 0; q < 4; ++q) { e[q] = expf(sv[q] - mx); se += e[q]; }
#pragma unroll
        for (int o = 16; o; o >>= 1) se += __shfl_xor_sync(0xffffffffu, se, o);
        float inv = 1.f / se;
#pragma unroll
        for (int q = 0; q < 4; ++q) {
            float ww = e[q] * inv;
            int i = lane + 32 * q;
            wsm[i] = ww;
            out[(size_t)NG * OUTD + (size_t)g * NODES + i] = ww;
        }
    }
    __syncthreads();

    // ---- pool: v[d] = sum_i w_i * (hi+lo)[i][d], split over 2 i-halves ----
    {
        int d = tid & 127, hseg = tid >> 7;
        float a = 0.f;
#pragma unroll 4
        for (int i = hseg * 64; i < hseg * 64 + 64; ++i) {
            u32 off = (u32)i * ZB_RS + (u32)d * 2;
            float zv = bf2f(*(unsigned short*)(smc + off))
                     + bf2f(*(unsigned short*)(smc + ZB_PL + off));
            a = fmaf(wsm[i], zv, a);
        }
        vpart[hseg * 128 + d] = a;
    }
    __syncthreads();
    if (tid < OUTD)
        out[(size_t)g * OUTD + tid] = vpart[tid] + vpart[128 + tid];
}

}  // namespace lb

extern "C" void kernel_launch(void* const* d_in, const int* in_sizes, int n_in,
                              void* d_out, int out_size)
{
    (void)in_sizes; (void)n_in; (void)out_size;
    const float* H     = (const float*)d_in[0];
    const float* W_in  = (const float*)d_in[2];
    const float* b_in  = (const float*)d_in[3];
    const float* g_in  = (const float*)d_in[4];
    const float* be_in = (const float*)d_in[5];
    const float* Wb    = (const float*)d_in[6];
    const float* bb    = (const float*)d_in[7];
    const float* gb    = (const float*)d_in[8];
    const float* betab = (const float*)d_in[9];
    const float* W_out = (const float*)d_in[10];
    const float* b_out = (const float*)d_in[11];
    const float* g_out = (const float*)d_in[12];
    const float* be_out= (const float*)d_in[13];
    float* out = (float*)d_out;

    lb::prep<<<960, 256>>>(W_in, Wb, W_out);

    cudaFuncSetAttribute(lb::mlp,
                         cudaFuncAttributeMaxDynamicSharedMemorySize,
                         lb::SMEM_A);
    cudaFuncSetAttribute(lb::pool,
                         cudaFuncAttributeMaxDynamicSharedMemorySize,
                         lb::SMEM_B);

    lb::mlp<<<2 * lb::NG, lb::TPA, lb::SMEM_A>>>(
        H, b_in, g_in, be_in, bb, gb, betab, b_out, g_out, be_out);
    lb::pool<<<lb::NG, lb::TPBB, lb::SMEM_B>>>(out);
}

// round 10
// speedup vs baseline: 1.2376x; 1.2376x over previous
#include <cuda_runtime.h>
#include <cuda_bf16.h>
#include <cstdint>

// ============================================================================
// LocalBranch round 10: R7 structure (623us) with weight staging switched from
// per-16B cp.async (LSU-issue-bound: 87K ops x ~2cyc = 174K cyc/CTA = measured
// kernel time) to cp.async.bulk + mbarrier (1 instruction per 40KB chunk).
//  - per-graph CTA, 512 thr = 16 warps, warp tile 32x64 (or 32x32)
//  - bf16x3 (hi/lo split, 3-term) GEMMs on mma.sync m16n8k16
//  - x as hi/lo bf16 planes in SMEM; weights pre-split into __device__ image
//  - 2-slot ring, bulk-copy double buffered; LN epilogues in fp32 registers
//  - Gram = Z @ Z^T same path; softmax/pool SIMT
// ============================================================================

namespace lb {

using u32 = uint32_t;

constexpr int TPB = 512, NODES = 128, IND = 64, HID = 256, OUTD = 128,
              NBLK = 3, NG = 1024;

// SMEM layout (bytes)
constexpr int XS_RS = 528;                 // x-plane row stride (264 bf16)
constexpr int XS_PL = 128 * XS_RS;         // 67584 per plane
constexpr int XS_HI = 0;
constexpr int XS_LO = XS_PL;
constexpr int RING  = 2 * XS_PL;           // 135168 (2 weight slots; later zT)
constexpr int SLOT  = 40960;
constexpr int SCR   = RING + 2 * SLOT;     // 217088
constexpr int SC_PART = SCR;               // float2[128*4]
constexpr int SC_SQ   = SCR + 4096;        // float[128]
constexpr int SC_S    = SCR + 4608;        // float[128]
constexpr int SC_W    = SCR + 5120;        // float[128]
constexpr int SC_MB   = SCR + 5632;        // 2 mbarriers (8 B each)
constexpr int SMEM_BYTES = SCR + 5648;     // 222736

// Weight image: per GEMM, k32 chunks; chunk = [hi plane][lo plane],
// plane = N rows x 40 bf16 (80 B, padded) in n-major (W^T) order.
constexpr int IMG_STEM = 0;                           // 2 chunks x 40960
constexpr int IMG_BLK  = 81920;                       // 3 x 8 x 40960
constexpr int IMG_BLKSTR = 327680;
constexpr int IMG_HEAD = 1064960;                     // 8 x 20480
__device__ __align__(128) unsigned char g_wimg[1228800];

// ---------------- PTX helpers ----------------
__device__ __forceinline__ u32 s2u(const void* p) {
    u32 a;
    asm("{ .reg .u64 t; cvta.to.shared.u64 t, %1; cvt.u32.u64 %0, t; }"
        : "=r"(a) : "l"(p));
    return a;
}
__device__ __forceinline__ void ldsm4(u32* r, u32 addr) {
    asm volatile("ldmatrix.sync.aligned.m8n8.x4.shared.b16 {%0,%1,%2,%3}, [%4];"
                 : "=r"(r[0]), "=r"(r[1]), "=r"(r[2]), "=r"(r[3]) : "r"(addr));
}
__device__ __forceinline__ void mma16816(float* c, const u32* a, u32 b0, u32 b1) {
    asm volatile(
        "mma.sync.aligned.m16n8k16.row.col.f32.bf16.bf16.f32 "
        "{%0,%1,%2,%3}, {%4,%5,%6,%7}, {%8,%9}, {%0,%1,%2,%3};"
        : "+f"(c[0]), "+f"(c[1]), "+f"(c[2]), "+f"(c[3])
        : "r"(a[0]), "r"(a[1]), "r"(a[2]), "r"(a[3]), "r"(b0), "r"(b1));
}
__device__ __forceinline__ void mbar_init(u32 mb, u32 c) {
    asm volatile("mbarrier.init.shared.b64 [%0], %1;" :: "r"(mb), "r"(c)
                 : "memory");
}
__device__ __forceinline__ void mbar_expect_tx(u32 mb, u32 tx) {
    asm volatile("mbarrier.arrive.expect_tx.shared.b64 _, [%0], %1;"
                 :: "r"(mb), "r"(tx) : "memory");
}
__device__ __forceinline__ void bulk_g2s(u32 dst, const void* src, u32 bytes,
                                         u32 mb) {
    asm volatile(
        "cp.async.bulk.shared::cta.global.mbarrier::complete_tx::bytes "
        "[%0], [%1], %2, [%3];"
        :: "r"(dst), "l"(src), "r"(bytes), "r"(mb) : "memory");
}
__device__ __forceinline__ void mbar_wait(u32 mb, u32 parity) {
    asm volatile(
        "{\n\t.reg .pred P;\n\t"
        "W%=:\n\t"
        "mbarrier.try_wait.parity.acquire.cta.shared::cta.b64 P, [%0], %1, 0x989680;\n\t"
        "@!P bra W%=;\n\t}"
        :: "r"(mb), "r"(parity) : "memory");
}

// ---------------- bf16 pack helpers ----------------
__device__ __forceinline__ u32 packbf(float x0, float x1) {
    unsigned short a = __bfloat16_as_ushort(__float2bfloat16(x0));
    unsigned short b = __bfloat16_as_ushort(__float2bfloat16(x1));
    return (u32)a | ((u32)b << 16);
}
__device__ __forceinline__ float bflo(u32 p) {
    return __bfloat162float(__ushort_as_bfloat16((unsigned short)(p & 0xffff)));
}
__device__ __forceinline__ float bfhi(u32 p) {
    return __bfloat162float(__ushort_as_bfloat16((unsigned short)(p >> 16)));
}

// ---------------- prep: weights -> split/transposed padded image ----------
__global__ void prep(const float* __restrict__ Wi, const float* __restrict__ Wb,
                     const float* __restrict__ Wo) {
    int idx = blockIdx.x * 256 + threadIdx.x;        // 245760 total
    const float* W; int k, n, N; long base; int cstr;
    if (idx < 16384) {
        W = Wi; N = 256; k = idx >> 8; n = idx & 255;
        base = IMG_STEM; cstr = 40960;
    } else if (idx < 212992) {
        int e = idx - 16384; int b = e >> 16; e &= 65535;
        W = Wb + (size_t)b * 65536; N = 256; k = e >> 8; n = e & 255;
        base = IMG_BLK + (long)b * IMG_BLKSTR; cstr = 40960;
    } else {
        int e = idx - 212992;
        W = Wo; N = 128; k = e >> 7; n = e & 127;
        base = IMG_HEAD; cstr = 20480;
    }
    float w = W[(size_t)k * N + n];
    __nv_bfloat16 h = __float2bfloat16(w);
    __nv_bfloat16 l = __float2bfloat16(w - __bfloat162float(h));
    long off = base + (long)(k >> 5) * cstr + (long)n * 80 + (k & 31) * 2;
    *(__nv_bfloat16*)(g_wimg + off) = h;
    *(__nv_bfloat16*)(g_wimg + off + (long)N * 80) = l;
}

// ---------------- staged GEMM: acc += X(planes) @ W(img), 3-term ----------
// Weight chunks arrive via cp.async.bulk (1 instr per 40KB) + mbarrier;
// 2-slot ring, double buffered. Term-major mma issue.
template<int N>   // 256 or 128
__device__ __forceinline__ void gemm_run(
    u32 smb, unsigned char* smc, const unsigned char* img, int nchunk,
    float (&acc)[2][8][4], int tid, int m0, int nq,
    int a_row, int a_kh, int b_n, int b_kh, int (&ph)[2])
{
    constexpr int NP = N / 64;                 // ldsm-pairs of n8 tiles (4|2)
    constexpr int NH = NP / 2;                 // halves of 2 pairs
    constexpr u32 CB = N * 160;                // chunk bytes (2 planes)
    const int n0 = nq * (N / 4);

    const u32 axh = smb + XS_HI + (u32)(m0 + a_row) * XS_RS + a_kh * 16;
    const u32 axl = axh + XS_PL;
    const u32 wtb = (u32)(n0 + b_n) * 80 + b_kh * 16;
    const u32 mb0 = smb + SC_MB;

#pragma unroll
    for (int mt = 0; mt < 2; ++mt)
#pragma unroll
        for (int nt = 0; nt < 8; ++nt)
#pragma unroll
            for (int e = 0; e < 4; ++e) acc[mt][nt][e] = 0.f;

    // entry sync: prior slot readers + plane writers done
    __syncthreads();
    if (tid == 0) {
        mbar_expect_tx(mb0, CB);
        bulk_g2s(smb + RING, img, CB, mb0);
        if (nchunk > 1) {
            mbar_expect_tx(mb0 + 8, CB);
            bulk_g2s(smb + RING + SLOT, img + CB, CB, mb0 + 8);
        }
    }

    for (int ch = 0; ch < nchunk; ++ch) {
        const int s = ch & 1;
        mbar_wait(mb0 + 8 * s, (u32)ph[s]);
        ph[s] ^= 1;
        const u32 slot = smb + RING + (u32)s * SLOT;
#pragma unroll
        for (int ks = 0; ks < 2; ++ks) {
            const u32 kb = (u32)ch * 64 + ks * 32;
            u32 ah0[4], ah1[4], al0[4], al1[4];
            ldsm4(ah0, axh + kb);
            ldsm4(ah1, axh + 16 * XS_RS + kb);
            ldsm4(al0, axl + kb);
            ldsm4(al1, axl + 16 * XS_RS + kb);
#pragma unroll
            for (int hf = 0; hf < NH; ++hf) {
                u32 bh[2][4], bl[2][4];
#pragma unroll
                for (int p = 0; p < 2; ++p) {
                    const u32 wa = slot + wtb
                                 + (u32)(hf * 2 + p) * 16 * 80 + ks * 32;
                    ldsm4(bh[p], wa);
                    ldsm4(bl[p], wa + N * 80);
                }
                // term 1: Ahi * Bhi
#pragma unroll
                for (int p = 0; p < 2; ++p)
#pragma unroll
                    for (int h = 0; h < 2; ++h) {
                        int nt = (hf * 2 + p) * 2 + h;
                        mma16816(acc[0][nt], ah0, bh[p][2*h], bh[p][2*h+1]);
                        mma16816(acc[1][nt], ah1, bh[p][2*h], bh[p][2*h+1]);
                    }
                // term 2: Alo * Bhi
#pragma unroll
                for (int p = 0; p < 2; ++p)
#pragma unroll
                    for (int h = 0; h < 2; ++h) {
                        int nt = (hf * 2 + p) * 2 + h;
                        mma16816(acc[0][nt], al0, bh[p][2*h], bh[p][2*h+1]);
                        mma16816(acc[1][nt], al1, bh[p][2*h], bh[p][2*h+1]);
                    }
                // term 3: Ahi * Blo
#pragma unroll
                for (int p = 0; p < 2; ++p)
#pragma unroll
                    for (int h = 0; h < 2; ++h) {
                        int nt = (hf * 2 + p) * 2 + h;
                        mma16816(acc[0][nt], ah0, bl[p][2*h], bl[p][2*h+1]);
                        mma16816(acc[1][nt], ah1, bl[p][2*h], bl[p][2*h+1]);
                    }
            }
        }
        if (ch + 2 < nchunk) {
            __syncthreads();   // all warps done reading slot s
            if (tid == 0) {
                mbar_expect_tx(mb0 + 8 * s, CB);
                bulk_g2s(slot, img + (size_t)(ch + 2) * CB, CB, mb0 + 8 * s);
            }
        }
    }
}

// ---------------- main kernel ----------------
__global__ void __launch_bounds__(TPB, 1)
fused(const float* __restrict__ H,
      const float* __restrict__ b_in, const float* __restrict__ g_in,
      const float* __restrict__ be_in,
      const float* __restrict__ bb, const float* __restrict__ gb,
      const float* __restrict__ betab,
      const float* __restrict__ b_out, const float* __restrict__ g_out,
      const float* __restrict__ be_out,
      float* __restrict__ out)
{
    extern __shared__ __align__(128) unsigned char smc[];
    const u32 smb = s2u(smc);
    const int tid = threadIdx.x, lane = tid & 31, w = tid >> 5;
    const int qr = lane >> 2, qc = lane & 3;
    const int mq = w & 3, nq = w >> 2;
    const int m0 = mq * 32;
    const int grp = lane >> 3, ri = lane & 7;
    const int a_row = (grp & 1) * 8 + ri, a_kh = grp >> 1;
    const int b_n = (grp >> 1) * 8 + ri,  b_kh = grp & 1;
    const int g = blockIdx.x;

    float2* part = (float2*)(smc + SC_PART);
    float* sqv = (float*)(smc + SC_SQ);
    float* ssm = (float*)(smc + SC_S);
    float* wsm = (float*)(smc + SC_W);
    int ph[2] = {0, 0};

    if (tid == 0) {
        mbar_init(smb + SC_MB, 1);
        mbar_init(smb + SC_MB + 8, 1);
    }

    // ---- stem A: H -> hi/lo bf16 planes (k = 0..63) ----
    {
        const int row = tid >> 2, c4 = tid & 3;
        const float4* hs = (const float4*)(H + (size_t)g * NODES * IND
                                           + (size_t)row * IND + c4 * 16);
        const u32 off = (u32)row * XS_RS + (u32)c4 * 32;
#pragma unroll
        for (int q = 0; q < 4; ++q) {
            float4 v = hs[q];
            u32 h0 = packbf(v.x, v.y), h1 = packbf(v.z, v.w);
            u32 l0 = packbf(v.x - bflo(h0), v.y - bfhi(h0));
            u32 l1 = packbf(v.z - bflo(h1), v.w - bfhi(h1));
            *(u32*)(smc + XS_HI + off + q * 8)     = h0;
            *(u32*)(smc + XS_HI + off + q * 8 + 4) = h1;
            *(u32*)(smc + XS_LO + off + q * 8)     = l0;
            *(u32*)(smc + XS_LO + off + q * 8 + 4) = l1;
        }
    }
    // (gemm_run's entry __syncthreads orders mbar init + plane STS)

    float acc[2][8][4];

    // ---- LN(+relu,+residual) epilogue for N=256, rewrites x planes ----
    auto ep256 = [&](const float* bias, const float* gam, const float* bet,
                     bool res) {
        const int n0 = nq * 64;
        float s1[4] = {0.f, 0.f, 0.f, 0.f}, s2[4] = {0.f, 0.f, 0.f, 0.f};
#pragma unroll
        for (int nt = 0; nt < 8; ++nt) {
            float2 bp = *(const float2*)&bias[n0 + nt * 8 + qc * 2];
#pragma unroll
            for (int mt = 0; mt < 2; ++mt) {
                float* c = acc[mt][nt];
                c[0] += bp.x; c[1] += bp.y; c[2] += bp.x; c[3] += bp.y;
                s1[mt*2]   += c[0] + c[1];
                s2[mt*2]    = fmaf(c[0], c[0], fmaf(c[1], c[1], s2[mt*2]));
                s1[mt*2+1] += c[2] + c[3];
                s2[mt*2+1]  = fmaf(c[2], c[2], fmaf(c[3], c[3], s2[mt*2+1]));
            }
        }
#pragma unroll
        for (int r = 0; r < 4; ++r) {
            s1[r] += __shfl_xor_sync(0xffffffffu, s1[r], 1);
            s1[r] += __shfl_xor_sync(0xffffffffu, s1[r], 2);
            s2[r] += __shfl_xor_sync(0xffffffffu, s2[r], 1);
            s2[r] += __shfl_xor_sync(0xffffffffu, s2[r], 2);
        }
        __syncthreads();   // all warps out of mma before part reuse
        if (qc == 0) {
#pragma unroll
            for (int r = 0; r < 4; ++r) {
                int row = m0 + (r >> 1) * 16 + (r & 1) * 8 + qr;
                part[row * 4 + nq] = make_float2(s1[r], s2[r]);
            }
        }
        __syncthreads();
        float mu[4], rs[4];
#pragma unroll
        for (int r = 0; r < 4; ++r) {
            int row = m0 + (r >> 1) * 16 + (r & 1) * 8 + qr;
            float4 p0 = *(float4*)&part[row * 4];
            float4 p1 = *(float4*)&part[row * 4 + 2];
            float S1 = p0.x + p0.z + p1.x + p1.z;
            float S2 = p0.y + p0.w + p1.y + p1.w;
            float m_ = S1 * (1.f / 256.f);
            mu[r] = m_;
            rs[r] = rsqrtf(fmaf(-m_, m_, S2 * (1.f / 256.f)) + 1e-5f);
        }
        __syncthreads();
#pragma unroll
        for (int nt = 0; nt < 8; ++nt) {
            int col = n0 + nt * 8 + qc * 2;
            float2 gg = *(const float2*)&gam[col];
            float2 ee = *(const float2*)&bet[col];
#pragma unroll
            for (int mt = 0; mt < 2; ++mt)
#pragma unroll
                for (int h = 0; h < 2; ++h) {
                    int r4 = mt * 2 + h;
                    int row = m0 + mt * 16 + h * 8 + qr;
                    float v0 = acc[mt][nt][2 * h], v1 = acc[mt][nt][2 * h + 1];
                    float y0 = fmaxf(fmaf((v0 - mu[r4]) * rs[r4], gg.x, ee.x), 0.f);
                    float y1 = fmaxf(fmaf((v1 - mu[r4]) * rs[r4], gg.y, ee.y), 0.f);
                    u32 off = (u32)row * XS_RS + (u32)col * 2;
                    if (res) {
                        u32 oh = *(u32*)(smc + XS_HI + off);
                        u32 ol = *(u32*)(smc + XS_LO + off);
                        y0 += bflo(oh) + bflo(ol);
                        y1 += bfhi(oh) + bfhi(ol);
                    }
                    u32 hh = packbf(y0, y1);
                    u32 ll = packbf(y0 - bflo(hh), y1 - bfhi(hh));
                    *(u32*)(smc + XS_HI + off) = hh;
                    *(u32*)(smc + XS_LO + off) = ll;
                }
        }
    };

    // ---- pipeline: stem + 3 residual blocks ----
    gemm_run<256>(smb, smc, g_wimg + IMG_STEM, 2, acc, tid, m0, nq,
                  a_row, a_kh, b_n, b_kh, ph);
    ep256(b_in, g_in, be_in, false);
    for (int b = 0; b < NBLK; ++b) {
        gemm_run<256>(smb, smc, g_wimg + IMG_BLK + (size_t)b * IMG_BLKSTR, 8,
                      acc, tid, m0, nq, a_row, a_kh, b_n, b_kh, ph);
        ep256(bb + b * HID, gb + b * HID, betab + b * HID, true);
    }

    // ---- head GEMM + epilogue: z = LN(x@W_out+b_out) ----
    gemm_run<128>(smb, smc, g_wimg + IMG_HEAD, 8, acc, tid, m0, nq,
                  a_row, a_kh, b_n, b_kh, ph);
    {
        const int n0 = nq * 32;
        float s1[4] = {0.f, 0.f, 0.f, 0.f}, s2[4] = {0.f, 0.f, 0.f, 0.f};
#pragma unroll
        for (int nt = 0; nt < 4; ++nt) {
            float2 bp = *(const float2*)&b_out[n0 + nt * 8 + qc * 2];
#pragma unroll
            for (int mt = 0; mt < 2; ++mt) {
                float* c = acc[mt][nt];
                c[0] += bp.x; c[1] += bp.y; c[2] += bp.x; c[3] += bp.y;
                s1[mt*2]   += c[0] + c[1];
                s2[mt*2]    = fmaf(c[0], c[0], fmaf(c[1], c[1], s2[mt*2]));
                s1[mt*2+1] += c[2] + c[3];
                s2[mt*2+1]  = fmaf(c[2], c[2], fmaf(c[3], c[3], s2[mt*2+1]));
            }
        }
#pragma unroll
        for (int r = 0; r < 4; ++r) {
            s1[r] += __shfl_xor_sync(0xffffffffu, s1[r], 1);
            s1[r] += __shfl_xor_sync(0xffffffffu, s1[r], 2);
            s2[r] += __shfl_xor_sync(0xffffffffu, s2[r], 1);
            s2[r] += __shfl_xor_sync(0xffffffffu, s2[r], 2);
        }
        __syncthreads();
        if (qc == 0) {
#pragma unroll
            for (int r = 0; r < 4; ++r) {
                int row = m0 + (r >> 1) * 16 + (r & 1) * 8 + qr;
                part[row * 4 + nq] = make_float2(s1[r], s2[r]);
            }
        }
        __syncthreads();
        float mu[4], rs[4];
#pragma unroll
        for (int r = 0; r < 4; ++r) {
            int row = m0 + (r >> 1) * 16 + (r & 1) * 8 + qr;
            float4 p0 = *(float4*)&part[row * 4];
            float4 p1 = *(float4*)&part[row * 4 + 2];
            float S1 = p0.x + p0.z + p1.x + p1.z;
            float S2 = p0.y + p0.w + p1.y + p1.w;
            float m_ = S1 * (1.f / 128.f);
            mu[r] = m_;
            rs[r] = rsqrtf(fmaf(-m_, m_, S2 * (1.f / 128.f)) + 1e-5f);
        }
        __syncthreads();
        float* ztf = (float*)(smc + RING);     // zT[dim][132] fp32 (ring free)
        float sqp[4] = {0.f, 0.f, 0.f, 0.f};
#pragma unroll
        for (int nt = 0; nt < 4; ++nt) {
            int col = n0 + nt * 8 + qc * 2;
            float2 gg = *(const float2*)&g_out[col];
            float2 ee = *(const float2*)&be_out[col];
#pragma unroll
            for (int mt = 0; mt < 2; ++mt)
#pragma unroll
                for (int h = 0; h < 2; ++h) {
                    int r4 = mt * 2 + h;
                    int row = m0 + mt * 16 + h * 8 + qr;
                    float z0 = fmaf((acc[mt][nt][2*h]   - mu[r4]) * rs[r4], gg.x, ee.x);
                    float z1 = fmaf((acc[mt][nt][2*h+1] - mu[r4]) * rs[r4], gg.y, ee.y);
                    u32 off = (u32)row * XS_RS + (u32)col * 2;
                    u32 hh = packbf(z0, z1);
                    u32 ll = packbf(z0 - bflo(hh), z1 - bfhi(hh));
                    *(u32*)(smc + XS_HI + off) = hh;   // z planes overlay x
                    *(u32*)(smc + XS_LO + off) = ll;
                    ztf[col * 132 + row] = z0;
                    ztf[(col + 1) * 132 + row] = z1;
                    sqp[r4] = fmaf(z0, z0, fmaf(z1, z1, sqp[r4]));
                }
        }
#pragma unroll
        for (int r = 0; r < 4; ++r) {
            sqp[r] += __shfl_xor_sync(0xffffffffu, sqp[r], 1);
            sqp[r] += __shfl_xor_sync(0xffffffffu, sqp[r], 2);
        }
        if (qc == 0) {
#pragma unroll
            for (int r = 0; r < 4; ++r) {
                int row = m0 + (r >> 1) * 16 + (r & 1) * 8 + qr;
                part[row * 4 + nq].x = sqp[r];
            }
        }
        __syncthreads();
        if (nq == 0 && qc == 0) {
#pragma unroll
            for (int r = 0; r < 4; ++r) {
                int row = m0 + (r >> 1) * 16 + (r & 1) * 8 + qr;
                sqv[row] = part[row*4].x + part[row*4+1].x
                         + part[row*4+2].x + part[row*4+3].x;
            }
        }
        __syncthreads();
    }

    // ---- Gram: dot(i,j) = z_i . z_j via bf16x3 mma, term-major order ----
    {
#pragma unroll
        for (int mt = 0; mt < 2; ++mt)
#pragma unroll
            for (int nt = 0; nt < 4; ++nt)
#pragma unroll
                for (int e = 0; e < 4; ++e) acc[mt][nt][e] = 0.f;
        const int n0 = nq * 32;
        const u32 azh = smb + XS_HI + (u32)(m0 + a_row) * XS_RS + a_kh * 16;
        const u32 azl = azh + XS_PL;
        const u32 bzh = smb + XS_HI + (u32)(n0 + b_n) * XS_RS + b_kh * 16;
        const u32 bzl = bzh + XS_PL;
#pragma unroll
        for (int ks = 0; ks < 8; ++ks) {
            const u32 kb = (u32)ks * 32;
            u32 ah0[4], ah1[4], al0[4], al1[4];
            ldsm4(ah0, azh + kb);
            ldsm4(ah1, azh + 16 * XS_RS + kb);
            ldsm4(al0, azl + kb);
            ldsm4(al1, azl + 16 * XS_RS + kb);
            u32 bh[2][4], bl[2][4];
#pragma unroll
            for (int p = 0; p < 2; ++p) {
                ldsm4(bh[p], bzh + (u32)p * 16 * XS_RS + kb);
                ldsm4(bl[p], bzl + (u32)p * 16 * XS_RS + kb);
            }
#pragma unroll
            for (int p = 0; p < 2; ++p)
#pragma unroll
                for (int h = 0; h < 2; ++h) {
                    int nt = p * 2 + h;
                    mma16816(acc[0][nt], ah0, bh[p][2*h], bh[p][2*h+1]);
                    mma16816(acc[1][nt], ah1, bh[p][2*h], bh[p][2*h+1]);
                }
#pragma unroll
            for (int p = 0; p < 2; ++p)
#pragma unroll
                for (int h = 0; h < 2; ++h) {
                    int nt = p * 2 + h;
                    mma16816(acc[0][nt], al0, bh[p][2*h], bh[p][2*h+1]);
                    mma16816(acc[1][nt], al1, bh[p][2*h], bh[p][2*h+1]);
                }
#pragma unroll
            for (int p = 0; p < 2; ++p)
#pragma unroll
                for (int h = 0; h < 2; ++h) {
                    int nt = p * 2 + h;
                    mma16816(acc[0][nt], ah0, bl[p][2*h], bl[p][2*h+1]);
                    mma16816(acc[1][nt], ah1, bl[p][2*h], bl[p][2*h+1]);
                }
        }
        // distances -> per-row sums
        float sa[4] = {0.f, 0.f, 0.f, 0.f};
#pragma unroll
        for (int nt = 0; nt < 4; ++nt) {
            int col = n0 + nt * 8 + qc * 2;
            float sc0 = sqv[col], sc1 = sqv[col + 1];
#pragma unroll
            for (int mt = 0; mt < 2; ++mt)
#pragma unroll
                for (int h = 0; h < 2; ++h) {
                    int r4 = mt * 2 + h;
                    int row = m0 + mt * 16 + h * 8 + qr;
                    float sr = sqv[row];
                    float d0 = sr + sc0 - 2.f * acc[mt][nt][2 * h];
                    float d1 = sr + sc1 - 2.f * acc[mt][nt][2 * h + 1];
                    float t0 = (col == row) ? 1e-6f
                               : sqrtf(fmaxf(d0, 0.f) + 1e-12f);
                    float t1 = (col + 1 == row) ? 1e-6f
                               : sqrtf(fmaxf(d1, 0.f) + 1e-12f);
                    sa[r4] += t0 + t1;
                }
        }
#pragma unroll
        for (int r = 0; r < 4; ++r) {
            sa[r] += __shfl_xor_sync(0xffffffffu, sa[r], 1);
            sa[r] += __shfl_xor_sync(0xffffffffu, sa[r], 2);
        }
        if (qc == 0) {
#pragma unroll
            for (int r = 0; r < 4; ++r) {
                int row = m0 + (r >> 1) * 16 + (r & 1) * 8 + qr;
                part[row * 4 + nq].x = sa[r];
            }
        }
        __syncthreads();
        if (nq == 0 && qc == 0) {
#pragma unroll
            for (int r = 0; r < 4; ++r) {
                int row = m0 + (r >> 1) * 16 + (r & 1) * 8 + qr;
                ssm[row] = (part[row*4].x + part[row*4+1].x
                          + part[row*4+2].x + part[row*4+3].x) * (1.f / 128.f);
            }
        }
        __syncthreads();
    }

    // ---- softmax over 128 logits (warp 0) ----
    if (w == 0) {
        const float sc = 1.f / 0.25f;
        float sv[4], mx = -1e30f;
#pragma unroll
        for (int q = 0; q < 4; ++q) {
            sv[q] = ssm[lane + 32 * q] * sc;
            mx = fmaxf(mx, sv[q]);
        }
#pragma unroll
        for (int o = 16; o; o >>= 1)
            mx = fmaxf(mx, __shfl_xor_sync(0xffffffffu, mx, o));
        float e[4], se = 0.f;
#pragma unroll
        for (int q = 0; q < 4; ++q) { e[q] = expf(sv[q] - mx); se += e[q]; }
#pragma unroll
        for (int o = 16; o; o >>= 1) se += __shfl_xor_sync(0xffffffffu, se, o);
        float inv = 1.f / se;
#pragma unroll
        for (int q = 0; q < 4; ++q) {
            float ww = e[q] * inv;
            int i = lane + 32 * q;
            wsm[i] = ww;
            out[(size_t)NG * OUTD + (size_t)g * NODES + i] = ww;
        }
    }
    __syncthreads();

    // ---- v[d] = sum_i w_i * zT[d][i] ----
    if (tid < OUTD) {
        const float* ztf = (const float*)(smc + RING);
        float a = 0.f;
#pragma unroll 4
        for (int i = 0; i < NODES; ++i)
            a = fmaf(wsm[i], ztf[tid * 132 + i], a);
        out[(size_t)g * OUTD + tid] = a;
    }
}

}  // namespace lb

extern "C" void kernel_launch(void* const* d_in, const int* in_sizes, int n_in,
                              void* d_out, int out_size)
{
    (void)in_sizes; (void)n_in; (void)out_size;
    const float* H     = (const float*)d_in[0];
    const float* W_in  = (const float*)d_in[2];
    const float* b_in  = (const float*)d_in[3];
    const float* g_in  = (const float*)d_in[4];
    const float* be_in = (const float*)d_in[5];
    const float* Wb    = (const float*)d_in[6];
    const float* bb    = (const float*)d_in[7];
    const float* gb    = (const float*)d_in[8];
    const float* betab = (const float*)d_in[9];
    const float* W_out = (const float*)d_in[10];
    const float* b_out = (const float*)d_in[11];
    const float* g_out = (const float*)d_in[12];
    const float* be_out= (const float*)d_in[13];
    float* out = (float*)d_out;

    lb::prep<<<960, 256>>>(W_in, Wb, W_out);

    cudaFuncSetAttribute(lb::fused,
                         cudaFuncAttributeMaxDynamicSharedMemorySize,
                         lb::SMEM_BYTES);
    lb::fused<<<lb::NG, lb::TPB, lb::SMEM_BYTES>>>(
        H, b_in, g_in, be_in, bb, gb, betab, b_out, g_out, be_out, out);
}

// round 11
// speedup vs baseline: 1.2682x; 1.0247x over previous
#include <cuda_runtime.h>
#include <cuda_bf16.h>
#include <cstdint>

// ============================================================================
// LocalBranch round 11: bf16x3 mma.sync + cp.async.bulk staging + M-split
// (2 CTAs/SM so one CTA's epilogues overlap the other's MMAs).
//  Kernel A (mlp): 2048 CTAs x 256 thr, 64 nodes each; weights in ldsm-ready
//    128B-tile-packed k16 chunks, 2-slot bulk ring (16KB slots); z -> g_z.
//  Kernel B (pool): 1024 CTAs x 256 thr; Gram via bf16x3 mma, softmax, pool.
// ============================================================================

namespace lb {

using u32 = uint32_t;

constexpr int NODES = 128, IND = 64, HID = 256, OUTD = 128, NBLK = 3, NG = 1024;

// ---- kernel A smem ----
constexpr int TPA   = 256;
constexpr int XA_RS = 528;               // x-plane row stride (bytes)
constexpr int XA_PL = 64 * XA_RS;        // 33792 per plane (64 rows)
constexpr int A_RING = 2 * XA_PL;        // 67584
constexpr int A_SLOTB = 16384;           // max chunk bytes (N=256)
constexpr int A_PART = A_RING + 2 * A_SLOTB;   // 100352: float2[64*4]
constexpr int A_MB   = A_PART + 2048;    // 102400: 2 mbarriers
constexpr int SMEM_A = A_MB + 48;        // 102448 (x2 = 204896 <= 228KB)

// ---- kernel B smem ----
constexpr int TPBB  = 256;
constexpr int ZB_RS = 272;               // z-plane row stride (bytes)
constexpr int ZB_PL = 128 * ZB_RS;       // 34816 per plane
constexpr int B_SQ   = 2 * ZB_PL;        // float[128]
constexpr int B_PART = B_SQ + 512;       // float[256]
constexpr int B_SSM  = B_PART + 1024;    // float[128]
constexpr int B_WSM  = B_SSM + 512;      // float[128]
constexpr int B_VP   = B_WSM + 512;      // float[256]
constexpr int SMEM_B = B_VP + 1024;      // 73216

// ---- weight image: k16 chunks of ldsm-ready 128B tiles, no padding.
// chunk = [hi plane N*32 B][lo plane N*32 B]; element (k,n) of a GEMM:
//   off = base + (k>>4)*N*64 + plane + (n>>4)*512
//       + (((n>>3)&1)*2 + ((k&15)>>3))*128 + (n&7)*16 + (k&7)*2
constexpr long IMG_STEM   = 0;                    // 4 chunks x 16384
constexpr long IMG_BLK    = 65536;                // 3 x 16 x 16384
constexpr long IMG_BLKSTR = 262144;
constexpr long IMG_HEAD   = 851968;               // 16 x 8192
__device__ __align__(128) unsigned char g_wimg[983040];
__device__ float g_z[(size_t)NG * NODES * OUTD];  // 64 MB scratch

// ---------------- PTX helpers ----------------
__device__ __forceinline__ u32 s2u(const void* p) {
    u32 a;
    asm("{ .reg .u64 t; cvta.to.shared.u64 t, %1; cvt.u32.u64 %0, t; }"
        : "=r"(a) : "l"(p));
    return a;
}
__device__ __forceinline__ void ldsm4(u32* r, u32 addr) {
    asm volatile("ldmatrix.sync.aligned.m8n8.x4.shared.b16 {%0,%1,%2,%3}, [%4];"
                 : "=r"(r[0]), "=r"(r[1]), "=r"(r[2]), "=r"(r[3]) : "r"(addr));
}
__device__ __forceinline__ void mma16816(float* c, const u32* a, u32 b0, u32 b1) {
    asm volatile(
        "mma.sync.aligned.m16n8k16.row.col.f32.bf16.bf16.f32 "
        "{%0,%1,%2,%3}, {%4,%5,%6,%7}, {%8,%9}, {%0,%1,%2,%3};"
        : "+f"(c[0]), "+f"(c[1]), "+f"(c[2]), "+f"(c[3])
        : "r"(a[0]), "r"(a[1]), "r"(a[2]), "r"(a[3]), "r"(b0), "r"(b1));
}
__device__ __forceinline__ void mbar_init(u32 mb, u32 c) {
    asm volatile("mbarrier.init.shared.b64 [%0], %1;" :: "r"(mb), "r"(c)
                 : "memory");
}
__device__ __forceinline__ void mbar_expect_tx(u32 mb, u32 tx) {
    asm volatile("mbarrier.arrive.expect_tx.shared.b64 _, [%0], %1;"
                 :: "r"(mb), "r"(tx) : "memory");
}
__device__ __forceinline__ void bulk_g2s(u32 dst, const void* src, u32 bytes,
                                         u32 mb) {
    asm volatile(
        "cp.async.bulk.shared::cta.global.mbarrier::complete_tx::bytes "
        "[%0], [%1], %2, [%3];"
        :: "r"(dst), "l"(src), "r"(bytes), "r"(mb) : "memory");
}
__device__ __forceinline__ void mbar_wait(u32 mb, u32 parity) {
    asm volatile(
        "{\n\t.reg .pred P;\n\t"
        "W%=:\n\t"
        "mbarrier.try_wait.parity.acquire.cta.shared::cta.b64 P, [%0], %1, 0x989680;\n\t"
        "@!P bra W%=;\n\t}"
        :: "r"(mb), "r"(parity) : "memory");
}

// ---------------- bf16 pack helpers ----------------
__device__ __forceinline__ u32 packbf(float x0, float x1) {
    unsigned short a = __bfloat16_as_ushort(__float2bfloat16(x0));
    unsigned short b = __bfloat16_as_ushort(__float2bfloat16(x1));
    return (u32)a | ((u32)b << 16);
}
__device__ __forceinline__ float bflo(u32 p) {
    return __bfloat162float(__ushort_as_bfloat16((unsigned short)(p & 0xffff)));
}
__device__ __forceinline__ float bfhi(u32 p) {
    return __bfloat162float(__ushort_as_bfloat16((unsigned short)(p >> 16)));
}
__device__ __forceinline__ float bf2f(unsigned short v) {
    return __bfloat162float(__ushort_as_bfloat16(v));
}
__device__ __forceinline__ float warpsum(float v) {
#pragma unroll
    for (int o = 16; o; o >>= 1) v += __shfl_xor_sync(0xffffffffu, v, o);
    return v;
}

// ---------------- prep: weights -> split, tile-packed k16-chunk image ------
__global__ void prep(const float* __restrict__ Wi, const float* __restrict__ Wb,
                     const float* __restrict__ Wo) {
    int idx = blockIdx.x * 256 + threadIdx.x;        // 245760 total
    const float* W; int k, n, N; long base;
    if (idx < 16384) {
        W = Wi; N = 256; k = idx >> 8; n = idx & 255; base = IMG_STEM;
    } else if (idx < 212992) {
        int e = idx - 16384; int b = e >> 16; e &= 65535;
        W = Wb + (size_t)b * 65536; N = 256; k = e >> 8; n = e & 255;
        base = IMG_BLK + (long)b * IMG_BLKSTR;
    } else {
        int e = idx - 212992;
        W = Wo; N = 128; k = e >> 7; n = e & 127; base = IMG_HEAD;
    }
    float w = W[(size_t)k * N + n];
    __nv_bfloat16 h = __float2bfloat16(w);
    __nv_bfloat16 l = __float2bfloat16(w - __bfloat162float(h));
    int kk = k & 15;
    long off = base + (long)(k >> 4) * ((long)N * 64)
             + (long)(n >> 4) * 512
             + (long)((((n >> 3) & 1) * 2 + (kk >> 3)) * 128)
             + (n & 7) * 16 + (kk & 7) * 2;
    *(__nv_bfloat16*)(g_wimg + off) = h;
    *(__nv_bfloat16*)(g_wimg + off + (long)N * 32) = l;
}

// ---------------- kernel A staged GEMM (k16 packed chunks, bulk ring) ------
template<int N>   // 256 or 128
__device__ __forceinline__ void gemmA(
    u32 smb, const unsigned char* img, int nchunk,
    float (&acc)[2][8][4], int tid, int lane, int m0, int nq,
    int a_row, int a_kh, int (&ph)[2])
{
    constexpr int NH = N / 128;            // n16-pair groups per warp (2|1)
    constexpr u32 CB = (u32)N * 64;        // chunk bytes (2 planes)
    const int n16b = nq * (N / 64);        // first n16 index for this warp

    const u32 axh = smb + (u32)(m0 + a_row) * XA_RS + a_kh * 16;
    const u32 axl = axh + XA_PL;
    const u32 mb0 = smb + A_MB;

#pragma unroll
    for (int mt = 0; mt < 2; ++mt)
#pragma unroll
        for (int nt = 0; nt < 8; ++nt)
#pragma unroll
            for (int e = 0; e < 4; ++e) acc[mt][nt][e] = 0.f;

    __syncthreads();   // prior slot readers + plane writers done
    if (tid == 0) {
        mbar_expect_tx(mb0, CB);
        bulk_g2s(smb + A_RING, img, CB, mb0);
        mbar_expect_tx(mb0 + 8, CB);
        bulk_g2s(smb + A_RING + A_SLOTB, img + CB, CB, mb0 + 8);
    }

    for (int ch = 0; ch < nchunk; ++ch) {
        const int s = ch & 1;
        mbar_wait(mb0 + 8 * s, (u32)ph[s]);
        ph[s] ^= 1;
        const u32 slot = smb + A_RING + (u32)s * A_SLOTB;
        const u32 kb = (u32)ch * 32;       // 16 k-values = 32 B in x planes

        u32 ah0[4], ah1[4], al0[4], al1[4];
        ldsm4(ah0, axh + kb);
        ldsm4(ah1, axh + 16 * XA_RS + kb);
        ldsm4(al0, axl + kb);
        ldsm4(al1, axl + 16 * XA_RS + kb);
#pragma unroll
        for (int hf = 0; hf < NH; ++hf) {
            u32 bh[2][4], bl[2][4];
#pragma unroll
            for (int p = 0; p < 2; ++p) {
                const u32 wa = slot + (u32)(n16b + hf * 2 + p) * 512
                             + (u32)lane * 16;
                ldsm4(bh[p], wa);
                ldsm4(bl[p], wa + (u32)N * 32);
            }
            // term 1: Ahi * Bhi
#pragma unroll
            for (int p = 0; p < 2; ++p)
#pragma unroll
                for (int h = 0; h < 2; ++h) {
                    int nt = (hf * 2 + p) * 2 + h;
                    mma16816(acc[0][nt], ah0, bh[p][2*h], bh[p][2*h+1]);
                    mma16816(acc[1][nt], ah1, bh[p][2*h], bh[p][2*h+1]);
                }
            // term 2: Alo * Bhi
#pragma unroll
            for (int p = 0; p < 2; ++p)
#pragma unroll
                for (int h = 0; h < 2; ++h) {
                    int nt = (hf * 2 + p) * 2 + h;
                    mma16816(acc[0][nt], al0, bh[p][2*h], bh[p][2*h+1]);
                    mma16816(acc[1][nt], al1, bh[p][2*h], bh[p][2*h+1]);
                }
            // term 3: Ahi * Blo
#pragma unroll
            for (int p = 0; p < 2; ++p)
#pragma unroll
                for (int h = 0; h < 2; ++h) {
                    int nt = (hf * 2 + p) * 2 + h;
                    mma16816(acc[0][nt], ah0, bl[p][2*h], bl[p][2*h+1]);
                    mma16816(acc[1][nt], ah1, bl[p][2*h], bl[p][2*h+1]);
                }
        }
        if (ch + 2 < nchunk) {
            __syncthreads();   // all warps done reading slot s
            if (tid == 0) {
                mbar_expect_tx(mb0 + 8 * s, CB);
                bulk_g2s(slot, img + (size_t)(ch + 2) * CB, CB, mb0 + 8 * s);
            }
        }
    }
}

// ---------------- kernel A: MLP over 64 nodes ----------------
__global__ void __launch_bounds__(TPA, 2)
mlp(const float* __restrict__ H,
    const float* __restrict__ b_in, const float* __restrict__ g_in,
    const float* __restrict__ be_in,
    const float* __restrict__ bb, const float* __restrict__ gb,
    const float* __restrict__ betab,
    const float* __restrict__ b_out, const float* __restrict__ g_out,
    const float* __restrict__ be_out)
{
    extern __shared__ __align__(128) unsigned char smc[];
    const u32 smb = s2u(smc);
    const int tid = threadIdx.x, lane = tid & 31, w = tid >> 5;
    const int qr = lane >> 2, qc = lane & 3;
    const int m0 = (w & 1) * 32, nq = w >> 1;
    const int grp = lane >> 3, ri = lane & 7;
    const int a_row = (grp & 1) * 8 + ri, a_kh = grp >> 1;
    const int g = blockIdx.x >> 1, mh = blockIdx.x & 1;

    float2* part = (float2*)(smc + A_PART);
    int ph[2] = {0, 0};

    if (tid == 0) {
        mbar_init(smb + A_MB, 1);
        mbar_init(smb + A_MB + 8, 1);
    }

    // ---- load H (64 rows, node base mh*64) -> hi/lo planes ----
    {
        const int row = tid >> 2, c4 = tid & 3;
        const float4* hs = (const float4*)(H + (size_t)g * NODES * IND
                                           + (size_t)(mh * 64 + row) * IND
                                           + c4 * 16);
        const u32 off = (u32)row * XA_RS + (u32)c4 * 32;
#pragma unroll
        for (int q = 0; q < 4; ++q) {
            float4 v = hs[q];
            u32 h0 = packbf(v.x, v.y), h1 = packbf(v.z, v.w);
            u32 l0 = packbf(v.x - bflo(h0), v.y - bfhi(h0));
            u32 l1 = packbf(v.z - bflo(h1), v.w - bfhi(h1));
            *(u32*)(smc + off + q * 8)             = h0;
            *(u32*)(smc + off + q * 8 + 4)         = h1;
            *(u32*)(smc + XA_PL + off + q * 8)     = l0;
            *(u32*)(smc + XA_PL + off + q * 8 + 4) = l1;
        }
    }
    // (gemmA's entry __syncthreads orders mbar init + plane STS)

    float acc[2][8][4];

    // ---- LN(+relu,+residual) epilogue N=256, rewrites x planes ----
    auto ep256 = [&](const float* bias, const float* gam, const float* bet,
                     bool res) {
        const int n0 = nq * 64;
        float s1[4] = {0.f, 0.f, 0.f, 0.f}, s2[4] = {0.f, 0.f, 0.f, 0.f};
#pragma unroll
        for (int nt = 0; nt < 8; ++nt) {
            float2 bp = *(const float2*)&bias[n0 + nt * 8 + qc * 2];
#pragma unroll
            for (int mt = 0; mt < 2; ++mt) {
                float* c = acc[mt][nt];
                c[0] += bp.x; c[1] += bp.y; c[2] += bp.x; c[3] += bp.y;
                s1[mt*2]   += c[0] + c[1];
                s2[mt*2]    = fmaf(c[0], c[0], fmaf(c[1], c[1], s2[mt*2]));
                s1[mt*2+1] += c[2] + c[3];
                s2[mt*2+1]  = fmaf(c[2], c[2], fmaf(c[3], c[3], s2[mt*2+1]));
            }
        }
#pragma unroll
        for (int r = 0; r < 4; ++r) {
            s1[r] += __shfl_xor_sync(0xffffffffu, s1[r], 1);
            s1[r] += __shfl_xor_sync(0xffffffffu, s1[r], 2);
            s2[r] += __shfl_xor_sync(0xffffffffu, s2[r], 1);
            s2[r] += __shfl_xor_sync(0xffffffffu, s2[r], 2);
        }
        __syncthreads();
        if (qc == 0) {
#pragma unroll
            for (int r = 0; r < 4; ++r) {
                int row = m0 + (r >> 1) * 16 + (r & 1) * 8 + qr;
                part[row * 4 + nq] = make_float2(s1[r], s2[r]);
            }
        }
        __syncthreads();
        float mu[4], rs[4];
#pragma unroll
        for (int r = 0; r < 4; ++r) {
            int row = m0 + (r >> 1) * 16 + (r & 1) * 8 + qr;
            float4 p0 = *(float4*)&part[row * 4];
            float4 p1 = *(float4*)&part[row * 4 + 2];
            float S1 = p0.x + p0.z + p1.x + p1.z;
            float S2 = p0.y + p0.w + p1.y + p1.w;
            float m_ = S1 * (1.f / 256.f);
            mu[r] = m_;
            rs[r] = rsqrtf(fmaf(-m_, m_, S2 * (1.f / 256.f)) + 1e-5f);
        }
        __syncthreads();
#pragma unroll
        for (int nt = 0; nt < 8; ++nt) {
            int col = n0 + nt * 8 + qc * 2;
            float2 gg = *(const float2*)&gam[col];
            float2 ee = *(const float2*)&bet[col];
#pragma unroll
            for (int mt = 0; mt < 2; ++mt)
#pragma unroll
                for (int h = 0; h < 2; ++h) {
                    int r4 = mt * 2 + h;
                    int row = m0 + mt * 16 + h * 8 + qr;
                    float v0 = acc[mt][nt][2 * h], v1 = acc[mt][nt][2 * h + 1];
                    float y0 = fmaxf(fmaf((v0 - mu[r4]) * rs[r4], gg.x, ee.x), 0.f);
                    float y1 = fmaxf(fmaf((v1 - mu[r4]) * rs[r4], gg.y, ee.y), 0.f);
                    u32 off = (u32)row * XA_RS + (u32)col * 2;
                    if (res) {
                        u32 oh = *(u32*)(smc + off);
                        u32 ol = *(u32*)(smc + XA_PL + off);
                        y0 += bflo(oh) + bflo(ol);
                        y1 += bfhi(oh) + bfhi(ol);
                    }
                    u32 hh = packbf(y0, y1);
                    u32 ll = packbf(y0 - bflo(hh), y1 - bfhi(hh));
                    *(u32*)(smc + off)         = hh;
                    *(u32*)(smc + XA_PL + off) = ll;
                }
        }
    };

    // ---- pipeline ----
    gemmA<256>(smb, g_wimg + IMG_STEM, 4, acc, tid, lane, m0, nq,
               a_row, a_kh, ph);
    ep256(b_in, g_in, be_in, false);
    for (int b = 0; b < NBLK; ++b) {
        gemmA<256>(smb, g_wimg + IMG_BLK + (size_t)b * IMG_BLKSTR, 16,
                   acc, tid, lane, m0, nq, a_row, a_kh, ph);
        ep256(bb + b * HID, gb + b * HID, betab + b * HID, true);
    }
    gemmA<128>(smb, g_wimg + IMG_HEAD, 16, acc, tid, lane, m0, nq,
               a_row, a_kh, ph);

    // ---- head epilogue: z = LN(.), write to g_z ----
    {
        const int n0 = nq * 32;
        float s1[4] = {0.f, 0.f, 0.f, 0.f}, s2[4] = {0.f, 0.f, 0.f, 0.f};
#pragma unroll
        for (int nt = 0; nt < 4; ++nt) {
            float2 bp = *(const float2*)&b_out[n0 + nt * 8 + qc * 2];
#pragma unroll
            for (int mt = 0; mt < 2; ++mt) {
                float* c = acc[mt][nt];
                c[0] += bp.x; c[1] += bp.y; c[2] += bp.x; c[3] += bp.y;
                s1[mt*2]   += c[0] + c[1];
                s2[mt*2]    = fmaf(c[0], c[0], fmaf(c[1], c[1], s2[mt*2]));
                s1[mt*2+1] += c[2] + c[3];
                s2[mt*2+1]  = fmaf(c[2], c[2], fmaf(c[3], c[3], s2[mt*2+1]));
            }
        }
#pragma unroll
        for (int r = 0; r < 4; ++r) {
            s1[r] += __shfl_xor_sync(0xffffffffu, s1[r], 1);
            s1[r] += __shfl_xor_sync(0xffffffffu, s1[r], 2);
            s2[r] += __shfl_xor_sync(0xffffffffu, s2[r], 1);
            s2[r] += __shfl_xor_sync(0xffffffffu, s2[r], 2);
        }
        __syncthreads();
        if (qc == 0) {
#pragma unroll
            for (int r = 0; r < 4; ++r) {
                int row = m0 + (r >> 1) * 16 + (r & 1) * 8 + qr;
                part[row * 4 + nq] = make_float2(s1[r], s2[r]);
            }
        }
        __syncthreads();
        float mu[4], rs[4];
#pragma unroll
        for (int r = 0; r < 4; ++r) {
            int row = m0 + (r >> 1) * 16 + (r & 1) * 8 + qr;
            float4 p0 = *(float4*)&part[row * 4];
            float4 p1 = *(float4*)&part[row * 4 + 2];
            float S1 = p0.x + p0.z + p1.x + p1.z;
            float S2 = p0.y + p0.w + p1.y + p1.w;
            float m_ = S1 * (1.f / 128.f);
            mu[r] = m_;
            rs[r] = rsqrtf(fmaf(-m_, m_, S2 * (1.f / 128.f)) + 1e-5f);
        }
        float* zbase = g_z + (size_t)g * (NODES * OUTD);
#pragma unroll
        for (int nt = 0; nt < 4; ++nt) {
            int col = n0 + nt * 8 + qc * 2;
            float2 gg = *(const float2*)&g_out[col];
            float2 ee = *(const float2*)&be_out[col];
#pragma unroll
            for (int mt = 0; mt < 2; ++mt)
#pragma unroll
                for (int h = 0; h < 2; ++h) {
                    int r4 = mt * 2 + h;
                    int row = m0 + mt * 16 + h * 8 + qr;
                    float z0 = fmaf((acc[mt][nt][2*h]   - mu[r4]) * rs[r4], gg.x, ee.x);
                    float z1 = fmaf((acc[mt][nt][2*h+1] - mu[r4]) * rs[r4], gg.y, ee.y);
                    *(float2*)(zbase + (size_t)(mh * 64 + row) * OUTD + col) =
                        make_float2(z0, z1);
                }
        }
    }
}

// ---------------- kernel B: Gram + distances + softmax + pool --------------
__global__ void __launch_bounds__(TPBB, 3)
pool(float* __restrict__ out)
{
    extern __shared__ __align__(16) unsigned char smc[];
    const u32 smb = s2u(smc);
    const int tid = threadIdx.x, lane = tid & 31, w = tid >> 5;
    const int qr = lane >> 2, qc = lane & 3;
    const int m0 = (w & 3) * 32, nh = w >> 2;
    const int n0 = nh * 64;
    const int grp = lane >> 3, ri = lane & 7;
    const int a_row = (grp & 1) * 8 + ri, a_kh = grp >> 1;
    const int b_n = (grp >> 1) * 8 + ri,  b_kh = grp & 1;
    const int g = blockIdx.x;

    float* sqf  = (float*)(smc + B_SQ);
    float* partf = (float*)(smc + B_PART);
    float* ssm  = (float*)(smc + B_SSM);
    float* wsm  = (float*)(smc + B_WSM);
    float* vpart = (float*)(smc + B_VP);

    // ---- load z, convert to hi/lo planes, row norms ----
    const float* zbase = g_z + (size_t)g * (NODES * OUTD);
#pragma unroll 1
    for (int j = 0; j < 16; ++j) {
        int r = w * 16 + j;
        float4 v = ((const float4*)(zbase + (size_t)r * OUTD))[lane];
        u32 h0 = packbf(v.x, v.y), h1 = packbf(v.z, v.w);
        u32 l0 = packbf(v.x - bflo(h0), v.y - bfhi(h0));
        u32 l1 = packbf(v.z - bflo(h1), v.w - bfhi(h1));
        u32 off = (u32)r * ZB_RS + (u32)lane * 8;
        *(u32*)(smc + off)             = h0;
        *(u32*)(smc + off + 4)         = h1;
        *(u32*)(smc + ZB_PL + off)     = l0;
        *(u32*)(smc + ZB_PL + off + 4) = l1;
        float sq = fmaf(v.x, v.x, fmaf(v.y, v.y, fmaf(v.z, v.z, v.w * v.w)));
        sq = warpsum(sq);
        if (lane == 0) sqf[r] = sq;
    }
    __syncthreads();

    // ---- Gram via bf16x3 mma (warp tile 32x64) ----
    float acc[2][8][4];
#pragma unroll
    for (int mt = 0; mt < 2; ++mt)
#pragma unroll
        for (int nt = 0; nt < 8; ++nt)
#pragma unroll
            for (int e = 0; e < 4; ++e) acc[mt][nt][e] = 0.f;

    const u32 azh = smb + (u32)(m0 + a_row) * ZB_RS + a_kh * 16;
    const u32 azl = azh + ZB_PL;
    const u32 bzh = smb + (u32)(n0 + b_n) * ZB_RS + b_kh * 16;
    const u32 bzl = bzh + ZB_PL;
#pragma unroll
    for (int ks = 0; ks < 8; ++ks) {
        const u32 kb = (u32)ks * 32;
        u32 ah0[4], ah1[4], al0[4], al1[4];
        ldsm4(ah0, azh + kb);
        ldsm4(ah1, azh + 16 * ZB_RS + kb);
        ldsm4(al0, azl + kb);
        ldsm4(al1, azl + 16 * ZB_RS + kb);
#pragma unroll
        for (int hf = 0; hf < 2; ++hf) {
            u32 bh[2][4], bl[2][4];
#pragma unroll
            for (int p = 0; p < 2; ++p) {
                const u32 wa = (u32)(hf * 2 + p) * 16 * ZB_RS + kb;
                ldsm4(bh[p], bzh + wa);
                ldsm4(bl[p], bzl + wa);
            }
#pragma unroll
            for (int p = 0; p < 2; ++p)
#pragma unroll
                for (int h = 0; h < 2; ++h) {
                    int nt = (hf * 2 + p) * 2 + h;
                    mma16816(acc[0][nt], ah0, bh[p][2*h], bh[p][2*h+1]);
                    mma16816(acc[1][nt], ah1, bh[p][2*h], bh[p][2*h+1]);
                }
#pragma unroll
            for (int p = 0; p < 2; ++p)
#pragma unroll
                for (int h = 0; h < 2; ++h) {
                    int nt = (hf * 2 + p) * 2 + h;
                    mma16816(acc[0][nt], al0, bh[p][2*h], bh[p][2*h+1]);
                    mma16816(acc[1][nt], al1, bh[p][2*h], bh[p][2*h+1]);
                }
#pragma unroll
            for (int p = 0; p < 2; ++p)
#pragma unroll
                for (int h = 0; h < 2; ++h) {
                    int nt = (hf * 2 + p) * 2 + h;
                    mma16816(acc[0][nt], ah0, bl[p][2*h], bl[p][2*h+1]);
                    mma16816(acc[1][nt], ah1, bl[p][2*h], bl[p][2*h+1]);
                }
        }
    }

    // ---- distances -> per-row sums ----
    float sa[4] = {0.f, 0.f, 0.f, 0.f};
#pragma unroll
    for (int nt = 0; nt < 8; ++nt) {
        int col = n0 + nt * 8 + qc * 2;
        float sc0 = sqf[col], sc1 = sqf[col + 1];
#pragma unroll
        for (int mt = 0; mt < 2; ++mt)
#pragma unroll
            for (int h = 0; h < 2; ++h) {
                int r4 = mt * 2 + h;
                int row = m0 + mt * 16 + h * 8 + qr;
                float sr = sqf[row];
                float d0 = sr + sc0 - 2.f * acc[mt][nt][2 * h];
                float d1 = sr + sc1 - 2.f * acc[mt][nt][2 * h + 1];
                float t0 = (col == row) ? 1e-6f : sqrtf(fmaxf(d0, 0.f) + 1e-12f);
                float t1 = (col + 1 == row) ? 1e-6f : sqrtf(fmaxf(d1, 0.f) + 1e-12f);
                sa[r4] += t0 + t1;
            }
    }
#pragma unroll
    for (int r = 0; r < 4; ++r) {
        sa[r] += __shfl_xor_sync(0xffffffffu, sa[r], 1);
        sa[r] += __shfl_xor_sync(0xffffffffu, sa[r], 2);
    }
    if (qc == 0) {
#pragma unroll
        for (int r = 0; r < 4; ++r) {
            int row = m0 + (r >> 1) * 16 + (r & 1) * 8 + qr;
            partf[row * 2 + nh] = sa[r];
        }
    }
    __syncthreads();
    if (tid < NODES)
        ssm[tid] = (partf[tid * 2] + partf[tid * 2 + 1]) * (1.f / 128.f);
    __syncthreads();

    // ---- softmax (warp 0) ----
    if (w == 0) {
        const float sc = 1.f / 0.25f;
        float sv[4], mx = -1e30f;
#pragma unroll
        for (int q = 0; q < 4; ++q) {
            sv[q] = ssm[lane + 32 * q] * sc;
            mx = fmaxf(mx, sv[q]);
        }
#pragma unroll
        for (int o = 16; o; o >>= 1)
            mx = fmaxf(mx, __shfl_xor_sync(0xffffffffu, mx, o));
        float e[4], se = 0.f;
#pragma unroll
        for (int q = 0; q < 4; ++q) { e[q] = expf(sv[q] - mx); se += e[q]; }
#pragma unroll
        for (int o = 16; o; o >>= 1) se += __shfl_xor_sync(0xffffffffu, se, o);
        float inv = 1.f / se;
#pragma unroll
        for (int q = 0; q < 4; ++q) {
            float ww = e[q] * inv;
            int i = lane + 32 * q;
            wsm[i] = ww;
            out[(size_t)NG * OUTD + (size_t)g * NODES + i] = ww;
        }
    }
    __syncthreads();

    // ---- pool: v[d] = sum_i w_i * (hi+lo)[i][d], split over 2 i-halves ----
    {
        int d = tid & 127, hseg = tid >> 7;
        float a = 0.f;
#pragma unroll 4
        for (int i = hseg * 64; i < hseg * 64 + 64; ++i) {
            u32 off = (u32)i * ZB_RS + (u32)d * 2;
            float zv = bf2f(*(unsigned short*)(smc + off))
                     + bf2f(*(unsigned short*)(smc + ZB_PL + off));
            a = fmaf(wsm[i], zv, a);
        }
        vpart[hseg * 128 + d] = a;
    }
    __syncthreads();
    if (tid < OUTD)
        out[(size_t)g * OUTD + tid] = vpart[tid] + vpart[128 + tid];
}

}  // namespace lb

extern "C" void kernel_launch(void* const* d_in, const int* in_sizes, int n_in,
                              void* d_out, int out_size)
{
    (void)in_sizes; (void)n_in; (void)out_size;
    const float* H     = (const float*)d_in[0];
    const float* W_in  = (const float*)d_in[2];
    const float* b_in  = (const float*)d_in[3];
    const float* g_in  = (const float*)d_in[4];
    const float* be_in = (const float*)d_in[5];
    const float* Wb    = (const float*)d_in[6];
    const float* bb    = (const float*)d_in[7];
    const float* gb    = (const float*)d_in[8];
    const float* betab = (const float*)d_in[9];
    const float* W_out = (const float*)d_in[10];
    const float* b_out = (const float*)d_in[11];
    const float* g_out = (const float*)d_in[12];
    const float* be_out= (const float*)d_in[13];
    float* out = (float*)d_out;

    lb::prep<<<960, 256>>>(W_in, Wb, W_out);

    cudaFuncSetAttribute(lb::mlp,
                         cudaFuncAttributeMaxDynamicSharedMemorySize,
                         lb::SMEM_A);
    cudaFuncSetAttribute(lb::pool,
                         cudaFuncAttributeMaxDynamicSharedMemorySize,
                         lb::SMEM_B);

    lb::mlp<<<2 * lb::NG, lb::TPA, lb::SMEM_A>>>(
        H, b_in, g_in, be_in, bb, gb, betab, b_out, g_out, be_out);
    lb::pool<<<lb::NG, lb::TPBB, lb::SMEM_B>>>(out);
}